// round 4
// baseline (speedup 1.0000x reference)
#include <cuda_runtime.h>
#include <math.h>

#define NC 16
#define MARGIN_F 0.3f
#define EPS_F 1e-8f

// ---------------- device-global scratch (no allocations allowed) -----------
__device__ int    g_first_idx[NC];
__device__ int    g_present[NC];
__device__ float  g_D16[NC * NC];
__device__ double g_rank_sum;
__device__ double g_per_sum;
__device__ unsigned long long g_count;

// ---------------- kernel 1: first-occurrence index per class + reset -------
// NOTE: targets arrive as int32 (JAX silently downcasts int64 without x64).
__global__ void k_setup(const int* __restrict__ targets, int B) {
    __shared__ int s_first[NC];
    int t = threadIdx.x;
    if (t < NC) s_first[t] = B;   // sentinel = "absent"
    __syncthreads();
    for (int i = t; i < B; i += blockDim.x) {
        int cl = targets[i];
        unsigned int c = (unsigned int)cl;
        if (c < NC) atomicMin(&s_first[c], i);
    }
    __syncthreads();
    if (t < NC) {
        int fi = s_first[t];
        g_present[t]   = (fi < B) ? 1 : 0;
        g_first_idx[t] = (fi < B) ? fi : 0;   // argmax over all-false returns 0; match it
    }
    if (t == 0) {
        g_rank_sum = 0.0;
        g_per_sum  = 0.0;
        g_count    = 0ull;
    }
}

// ---------------- kernel 2: 16x16 distance matrix (one block per pair) -----
// dist = sqrt(max(|xi|^2 + |xj|^2 - 2*xi.xj, 1e-12))  -- mirrors reference
__global__ void k_dist(const float* __restrict__ x, int D, int B) {
    int pair = blockIdx.x;             // 0..255
    int i = pair >> 4;
    int j = pair & 15;
    int fi = g_first_idx[i];
    int fj = g_first_idx[j];
    if (fi < 0 || fi >= B) fi = 0;     // hard guard, no-op on valid data
    if (fj < 0 || fj >= B) fj = 0;
    const float4* xi4 = (const float4*)(x + (size_t)fi * (size_t)D);
    const float4* xj4 = (const float4*)(x + (size_t)fj * (size_t)D);

    float sii = 0.f, sjj = 0.f, sij = 0.f;
    int nv4 = D >> 2;
    for (int k = threadIdx.x; k < nv4; k += blockDim.x) {
        float4 a = xi4[k];
        float4 b = xj4[k];
        sii += a.x * a.x + a.y * a.y + a.z * a.z + a.w * a.w;
        sjj += b.x * b.x + b.y * b.y + b.z * b.z + b.w * b.w;
        sij += a.x * b.x + a.y * b.y + a.z * b.z + a.w * b.w;
    }
    for (int off = 16; off > 0; off >>= 1) {
        sii += __shfl_down_sync(0xFFFFFFFFu, sii, off);
        sjj += __shfl_down_sync(0xFFFFFFFFu, sjj, off);
        sij += __shfl_down_sync(0xFFFFFFFFu, sij, off);
    }
    __shared__ float r0[4], r1[4], r2[4];     // 128 threads = 4 warps
    int wid = threadIdx.x >> 5;
    int lid = threadIdx.x & 31;
    if (lid == 0) { r0[wid] = sii; r1[wid] = sjj; r2[wid] = sij; }
    __syncthreads();
    if (threadIdx.x == 0) {
        float a = 0.f, b = 0.f, c = 0.f;
        int nw = (blockDim.x + 31) >> 5;
        for (int w = 0; w < nw; w++) { a += r0[w]; b += r1[w]; c += r2[w]; }
        float d2 = a + b - 2.0f * c;
        d2 = fmaxf(d2, 1e-12f);
        g_D16[pair] = sqrtf(d2);
    }
}

// ---------------- kernel 3: streaming triplet reduction --------------------
// user_answers arrive as int32 (same JAX downcast).
__global__ void k_trip(const int* __restrict__ ua, int T) {
    __shared__ float sD[NC * NC];
    __shared__ int   sP[NC];
    for (int k = threadIdx.x; k < NC * NC; k += blockDim.x) sD[k] = g_D16[k];
    if (threadIdx.x < NC) sP[threadIdx.x] = g_present[threadIdx.x];
    __syncthreads();

    double rsum = 0.0, psum = 0.0;
    unsigned int cnt = 0;

    int idx    = blockIdx.x * blockDim.x + threadIdx.x;
    int stride = gridDim.x * blockDim.x;
    for (int t = idx; t < T; t += stride) {
        int a = ua[3 * t + 0];
        int p = ua[3 * t + 1];
        int n = ua[3 * t + 2];
        unsigned int ca = (unsigned int)a, cp = (unsigned int)p, cn = (unsigned int)n;
        bool inb = (ca < NC) && (cp < NC) && (cn < NC);   // range guard -> no traps ever
        if (inb && (sP[ca] & sP[cp] & sP[cn])) {
            float dap = sD[ca * NC + cp];
            float dan = sD[ca * NC + cn];
            rsum += (double)fmaxf(dap - dan + MARGIN_F, 0.0f);
            float sap = 1.0f / (dap + 1.0f);
            float san = 1.0f / (dan + 1.0f);
            float pap = sap / (sap + san);
            psum += (double)(-logf(pap + EPS_F));
            cnt++;
        }
    }

    for (int off = 16; off > 0; off >>= 1) {
        rsum += __shfl_down_sync(0xFFFFFFFFu, rsum, off);
        psum += __shfl_down_sync(0xFFFFFFFFu, psum, off);
        cnt  += __shfl_down_sync(0xFFFFFFFFu, cnt,  off);
    }
    __shared__ double wr[8], wp[8];
    __shared__ unsigned int wc[8];
    int wid = threadIdx.x >> 5;
    int lid = threadIdx.x & 31;
    if (lid == 0) { wr[wid] = rsum; wp[wid] = psum; wc[wid] = cnt; }
    __syncthreads();
    if (threadIdx.x == 0) {
        double R = 0.0, P = 0.0;
        unsigned int C = 0;
        int nw = (blockDim.x + 31) >> 5;
        for (int w = 0; w < nw; w++) { R += wr[w]; P += wp[w]; C += wc[w]; }
        atomicAdd(&g_rank_sum, R);
        atomicAdd(&g_per_sum,  P);
        atomicAdd(&g_count, (unsigned long long)C);
    }
}

// ---------------- kernel 4: finalize ---------------------------------------
__global__ void k_final(float* __restrict__ out, int out_n) {
    double nv = (double)g_count;
    if (nv < 1.0) nv = 1.0;
    float lh = (float)(g_rank_sum / nv);
    float lp = (float)(g_per_sum / nv);
    if (out_n > 0) out[0] = lh + lp;   // W_HUMAN * lh + W_PER * lp, both = 1
    if (out_n > 1) out[1] = lh;
    if (out_n > 2) out[2] = lp;
}

// ---------------- launch ----------------------------------------------------
// Inputs identified BY SIZE (robust to metadata ordering):
//   inputs       : largest element count             (4096*1024 = 4194304)
//   user_answers : only remaining size divisible by 3 (100000*3 = 300000)
//   targets_mat  : FIRST entry with the minimum size  (4096; targets_sub is the
//                  second 4096 entry, dict order preserved)
extern "C" void kernel_launch(void* const* d_in, const int* in_sizes, int n_in,
                              void* d_out, int out_size) {
    int idx_inputs = -1, idx_ua = -1, idx_tm = -1;
    int max_sz = -1;
    for (int i = 0; i < n_in; i++)
        if (in_sizes[i] > max_sz) { max_sz = in_sizes[i]; idx_inputs = i; }
    for (int i = 0; i < n_in; i++) {
        if (i == idx_inputs) continue;
        if ((in_sizes[i] % 3) == 0) { idx_ua = i; break; }
    }
    int min_sz = 0x7fffffff;
    for (int i = 0; i < n_in; i++) {
        if (i == idx_inputs || i == idx_ua) continue;
        if (in_sizes[i] < min_sz) min_sz = in_sizes[i];
    }
    for (int i = 0; i < n_in; i++) {
        if (i == idx_inputs || i == idx_ua) continue;
        if (in_sizes[i] == min_sz) { idx_tm = i; break; }   // first occurrence
    }
    if (idx_inputs < 0 || idx_ua < 0 || idx_tm < 0) return;

    const float* inputs   = (const float*)d_in[idx_inputs];
    const int*   targets  = (const int*)d_in[idx_tm];      // int32 (JAX downcast)
    const int*   user_ans = (const int*)d_in[idx_ua];      // int32 (JAX downcast)
    float* out = (float*)d_out;

    int B = in_sizes[idx_tm];
    int D = in_sizes[idx_inputs] / B;
    int T = in_sizes[idx_ua] / 3;

    k_setup<<<1, 256>>>(targets, B);
    k_dist<<<NC * NC, 128>>>(inputs, D, B);
    k_trip<<<256, 256>>>(user_ans, T);
    k_final<<<1, 1>>>(out, out_size);
}

// round 6
// speedup vs baseline: 1.2959x; 1.2959x over previous
#include <cuda_runtime.h>
#include <math.h>

#define NC 16
#define MARGIN_F 0.3f
#define EPS_F 1e-8f
#define NBLK 256
#define NTHR 256

// ---------------- device-global scratch (no allocations allowed) -----------
// All of these are reset by the LAST block of every kernel run, so each graph
// replay starts from a clean state.
__device__ float  g_D16[NC * NC];
__device__ int    g_dist_done   = 0;
__device__ int    g_blocks_done = 0;
__device__ double g_rank_sum    = 0.0;
__device__ double g_per_sum     = 0.0;
__device__ unsigned long long g_count = 0ull;

__global__ void __launch_bounds__(NTHR) k_fused(
    const float* __restrict__ x,        // inputs  [B, D]
    const int*   __restrict__ targets,  // targets_mat [B] (int32: JAX downcast)
    const int*   __restrict__ ua,       // user_answers [T, 3] (int32)
    float*       __restrict__ out,
    int B, int D, int T, int out_n)
{
    __shared__ int    s_first[NC];
    __shared__ float  sD[NC * NC];
    __shared__ float  sred0[NTHR / 32], sred1[NTHR / 32], sred2[NTHR / 32];
    __shared__ double wr[NTHR / 32], wp[NTHR / 32];
    __shared__ unsigned int wc[NTHR / 32];

    const int tid = threadIdx.x;
    const int bid = blockIdx.x;

    // ---- Phase 1: block-local first-occurrence scan (redundant per block) --
    if (tid < NC) s_first[tid] = B;          // sentinel = absent
    __syncthreads();
    for (int i = tid; i < B; i += NTHR) {
        unsigned int c = (unsigned int)targets[i];
        if (c < NC) atomicMin(&s_first[c], i);
    }
    __syncthreads();

    // ---- Phase 2: this block computes dist for pair (bid>>4, bid&15) ------
    {
        int i = bid >> 4, j = bid & 15;
        int fi = s_first[i];
        int fj = s_first[j];
        if (fi >= B) fi = 0;                 // argmax-over-all-false == 0
        if (fj >= B) fj = 0;
        const float4* xi4 = (const float4*)(x + (size_t)fi * (size_t)D);
        const float4* xj4 = (const float4*)(x + (size_t)fj * (size_t)D);

        float sii = 0.f, sjj = 0.f, sij = 0.f;
        int nv4 = D >> 2;                    // D=1024 -> 256 float4 = 1/thread
        for (int k = tid; k < nv4; k += NTHR) {
            float4 a = xi4[k];
            float4 b = xj4[k];
            sii += a.x * a.x + a.y * a.y + a.z * a.z + a.w * a.w;
            sjj += b.x * b.x + b.y * b.y + b.z * b.z + b.w * b.w;
            sij += a.x * b.x + a.y * b.y + a.z * b.z + a.w * b.w;
        }
        for (int off = 16; off > 0; off >>= 1) {
            sii += __shfl_down_sync(0xFFFFFFFFu, sii, off);
            sjj += __shfl_down_sync(0xFFFFFFFFu, sjj, off);
            sij += __shfl_down_sync(0xFFFFFFFFu, sij, off);
        }
        int w = tid >> 5, l = tid & 31;
        if (l == 0) { sred0[w] = sii; sred1[w] = sjj; sred2[w] = sij; }
        __syncthreads();
        if (tid == 0) {
            float a = 0.f, b = 0.f, c = 0.f;
            for (int w2 = 0; w2 < NTHR / 32; w2++) {
                a += sred0[w2]; b += sred1[w2]; c += sred2[w2];
            }
            float d2 = fmaxf(a + b - 2.0f * c, 1e-12f);
            g_D16[bid] = sqrtf(d2);
            __threadfence();                 // publish D16 before counting it
            atomicAdd(&g_dist_done, 1);
        }
    }

    // ---- Phase 3: wait for all 256 pairs (all blocks are co-resident) -----
    if (tid == 0) {
        while (atomicAdd(&g_dist_done, 0) < NBLK) { __nanosleep(32); }
    }
    __syncthreads();
    __threadfence();
    {   // volatile: force L2 reads (L1 not coherent across SMs)
        volatile float* vD = g_D16;
        for (int k = tid; k < NC * NC; k += NTHR) sD[k] = vD[k];
    }
    __syncthreads();

    // ---- Phase 4: streaming triplet reduction -----------------------------
    double rsum = 0.0, psum = 0.0;
    unsigned int cnt = 0;
    for (int t = bid * NTHR + tid; t < T; t += NBLK * NTHR) {
        int a = ua[3 * t + 0];
        int p = ua[3 * t + 1];
        int n = ua[3 * t + 2];
        unsigned int ca = (unsigned int)a, cp = (unsigned int)p, cn = (unsigned int)n;
        bool ok = (ca < NC) && (cp < NC) && (cn < NC) &&
                  (s_first[ca] < B) && (s_first[cp] < B) && (s_first[cn] < B);
        if (ok) {
            float dap = sD[ca * NC + cp];
            float dan = sD[ca * NC + cn];
            rsum += (double)fmaxf(dap - dan + MARGIN_F, 0.0f);
            float sap = 1.0f / (dap + 1.0f);
            float san = 1.0f / (dan + 1.0f);
            float pap = sap / (sap + san);
            psum += (double)(-logf(pap + EPS_F));
            cnt++;
        }
    }
    for (int off = 16; off > 0; off >>= 1) {
        rsum += __shfl_down_sync(0xFFFFFFFFu, rsum, off);
        psum += __shfl_down_sync(0xFFFFFFFFu, psum, off);
        cnt  += __shfl_down_sync(0xFFFFFFFFu, cnt,  off);
    }
    {
        int w = tid >> 5, l = tid & 31;
        if (l == 0) { wr[w] = rsum; wp[w] = psum; wc[w] = cnt; }
    }
    __syncthreads();

    // ---- Phase 5: block atomics + last-block finalize & state reset -------
    if (tid == 0) {
        double R = 0.0, P = 0.0;
        unsigned int C = 0;
        for (int w = 0; w < NTHR / 32; w++) { R += wr[w]; P += wp[w]; C += wc[w]; }
        atomicAdd(&g_rank_sum, R);
        atomicAdd(&g_per_sum,  P);
        atomicAdd(&g_count, (unsigned long long)C);
        __threadfence();
        int done = atomicAdd(&g_blocks_done, 1);
        if (done == NBLK - 1) {              // I'm the last block: finalize
            __threadfence();
            double R2 = atomicAdd(&g_rank_sum, 0.0);
            double P2 = atomicAdd(&g_per_sum,  0.0);
            unsigned long long C2 = atomicAdd(&g_count, 0ull);
            double nv = (double)C2;
            if (nv < 1.0) nv = 1.0;
            float lh = (float)(R2 / nv);
            float lp = (float)(P2 / nv);
            if (out_n > 0) out[0] = lh + lp;  // W_HUMAN=W_PER=1
            if (out_n > 1) out[1] = lh;
            if (out_n > 2) out[2] = lp;
            // reset for next graph replay
            g_rank_sum = 0.0;
            g_per_sum  = 0.0;
            g_count    = 0ull;
            g_dist_done   = 0;
            g_blocks_done = 0;
            __threadfence();
        }
    }
}

// ---------------- launch ----------------------------------------------------
// Inputs identified BY SIZE (robust to metadata ordering):
//   inputs       : largest element count              (4096*1024 = 4194304)
//   user_answers : only remaining size divisible by 3 (100000*3  = 300000)
//   targets_mat  : FIRST entry with the minimum size  (4096; targets_sub is
//                  the second 4096 entry, dict order preserved)
extern "C" void kernel_launch(void* const* d_in, const int* in_sizes, int n_in,
                              void* d_out, int out_size) {
    int idx_inputs = -1, idx_ua = -1, idx_tm = -1;
    int max_sz = -1;
    for (int i = 0; i < n_in; i++)
        if (in_sizes[i] > max_sz) { max_sz = in_sizes[i]; idx_inputs = i; }
    for (int i = 0; i < n_in; i++) {
        if (i == idx_inputs) continue;
        if ((in_sizes[i] % 3) == 0) { idx_ua = i; break; }
    }
    int min_sz = 0x7fffffff;
    for (int i = 0; i < n_in; i++) {
        if (i == idx_inputs || i == idx_ua) continue;
        if (in_sizes[i] < min_sz) min_sz = in_sizes[i];
    }
    for (int i = 0; i < n_in; i++) {
        if (i == idx_inputs || i == idx_ua) continue;
        if (in_sizes[i] == min_sz) { idx_tm = i; break; }   // first occurrence
    }
    if (idx_inputs < 0 || idx_ua < 0 || idx_tm < 0) return;

    const float* inputs   = (const float*)d_in[idx_inputs];
    const int*   targets  = (const int*)d_in[idx_tm];
    const int*   user_ans = (const int*)d_in[idx_ua];
    float* out = (float*)d_out;

    int B = in_sizes[idx_tm];
    int D = in_sizes[idx_inputs] / B;
    int T = in_sizes[idx_ua] / 3;

    k_fused<<<NBLK, NTHR>>>(inputs, targets, user_ans, out, B, D, T, out_size);
}